// round 1
// baseline (speedup 1.0000x reference)
#include <cuda_runtime.h>
#include <cstddef>

#define DIM   2048
#define TDIM  6144          // 3*DIM
#define BB    2
#define TT    8192
#define MROWS (BB*TT)       // 16384
#define WSZ   128
#define NBLK  (MROWS/WSZ)   // 128 (b,w) blocks total

// Scratch (static device globals: allocation-free per harness rules)
__device__ float g_qkv[(size_t)MROWS * TDIM];        // 402.7 MB: [q|k|v] per row
__device__ float g_attnw[(size_t)NBLK * WSZ * 256];  // 16.8 MB: relu^2 attention weights
__device__ float g_att[(size_t)MROWS * DIM];         // 134 MB: attention output

// ---------------------------------------------------------------------------
// C[M,N] = A[M,K] @ B[N,K]^T   (both K-contiguous row-major)
// 128x128 block tile, 16 k-chunk, 256 threads, 8x8 per-thread tile.
// Columns n < scale_cols are multiplied by `scale` (used to fold q/W into qkv).
// ---------------------------------------------------------------------------
__global__ __launch_bounds__(256) void sgemm_abt(
    const float* __restrict__ A, const float* __restrict__ B, float* __restrict__ C,
    int M, int N, int K, int scale_cols, float scale)
{
    __shared__ float As[16][129];
    __shared__ float Bs[16][129];
    const int tid = threadIdx.x;
    const int ty = tid >> 4, tx = tid & 15;
    const int m0 = blockIdx.y << 7;
    const int n0 = blockIdx.x << 7;
    const float* Ab = A + (size_t)m0 * K;
    const float* Bb = B + (size_t)n0 * K;

    float acc[8][8];
    #pragma unroll
    for (int r = 0; r < 8; r++)
        #pragma unroll
        for (int c = 0; c < 8; c++) acc[r][c] = 0.f;

    for (int k0 = 0; k0 < K; k0 += 16) {
        #pragma unroll
        for (int i = 0; i < 2; i++) {
            int idx = tid + (i << 8);        // float4 index in 128x16 tile
            int row = idx >> 2;              // 4 float4 per row
            int kc  = (idx & 3) << 2;
            float4 va = *(const float4*)(Ab + (size_t)row * K + k0 + kc);
            As[kc+0][row] = va.x; As[kc+1][row] = va.y;
            As[kc+2][row] = va.z; As[kc+3][row] = va.w;
            float4 vb = *(const float4*)(Bb + (size_t)row * K + k0 + kc);
            Bs[kc+0][row] = vb.x; Bs[kc+1][row] = vb.y;
            Bs[kc+2][row] = vb.z; Bs[kc+3][row] = vb.w;
        }
        __syncthreads();
        #pragma unroll
        for (int kk = 0; kk < 16; kk++) {
            float a[8], b[8];
            #pragma unroll
            for (int r = 0; r < 8; r++) a[r] = As[kk][ty + (r << 4)];
            #pragma unroll
            for (int c = 0; c < 8; c++) b[c] = Bs[kk][tx + (c << 4)];
            #pragma unroll
            for (int r = 0; r < 8; r++)
                #pragma unroll
                for (int c = 0; c < 8; c++)
                    acc[r][c] = fmaf(a[r], b[c], acc[r][c]);
        }
        __syncthreads();
    }

    #pragma unroll
    for (int r = 0; r < 8; r++) {
        int m = m0 + ty + (r << 4);
        #pragma unroll
        for (int c = 0; c < 8; c++) {
            int n = n0 + tx + (c << 4);
            float v = acc[r][c];
            if (n < scale_cols) v *= scale;
            C[(size_t)m * N + n] = v;
        }
    }
}

// ---------------------------------------------------------------------------
// attn_sim: for each (b,wblk) block compute sim = q_blk @ [k_prev|k_cur]^T over
// D=2048, apply sliding-window mask + relu^2, write 128x256 weights to g_attnw.
// ---------------------------------------------------------------------------
__global__ __launch_bounds__(256) void attn_sim_kernel(
    const float* __restrict__ qkv, float* __restrict__ attnw)
{
    __shared__ float Qs[16][129];
    __shared__ float Ks[16][257];
    const int tid = threadIdx.x;
    const int ty = tid >> 4, tx = tid & 15;
    const int blk = blockIdx.x;          // 0..127
    const int b = blk >> 6;
    const int wblk = blk & 63;
    const int qbase = b * TT + wblk * WSZ;   // global row of query 0
    const int kbase = qbase - WSZ;           // global row of key j=0
    const int bstart = b * TT;

    float acc[8][16];
    #pragma unroll
    for (int r = 0; r < 8; r++)
        #pragma unroll
        for (int c = 0; c < 16; c++) acc[r][c] = 0.f;

    for (int k0 = 0; k0 < DIM; k0 += 16) {
        // Q tile: 128 rows x 16 k  (512 float4, 2 per thread)
        #pragma unroll
        for (int i = 0; i < 2; i++) {
            int idx = tid + (i << 8);
            int row = idx >> 2;
            int kc  = (idx & 3) << 2;
            float4 v = *(const float4*)(qkv + (size_t)(qbase + row) * TDIM + k0 + kc);
            Qs[kc+0][row] = v.x; Qs[kc+1][row] = v.y;
            Qs[kc+2][row] = v.z; Qs[kc+3][row] = v.w;
        }
        // K tile: 256 rows x 16 k (1024 float4, 4 per thread), guard prev block
        #pragma unroll
        for (int i = 0; i < 4; i++) {
            int idx = tid + (i << 8);
            int row = idx >> 2;
            int kc  = (idx & 3) << 2;
            int gr = kbase + row;
            float4 v = make_float4(0.f, 0.f, 0.f, 0.f);
            if (gr >= bstart)
                v = *(const float4*)(qkv + (size_t)gr * TDIM + DIM + k0 + kc);
            Ks[kc+0][row] = v.x; Ks[kc+1][row] = v.y;
            Ks[kc+2][row] = v.z; Ks[kc+3][row] = v.w;
        }
        __syncthreads();
        #pragma unroll
        for (int kk = 0; kk < 16; kk++) {
            float a[8], kb[16];
            #pragma unroll
            for (int r = 0; r < 8; r++) a[r] = Qs[kk][ty + (r << 4)];
            #pragma unroll
            for (int c = 0; c < 16; c++) kb[c] = Ks[kk][tx + (c << 4)];
            #pragma unroll
            for (int r = 0; r < 8; r++)
                #pragma unroll
                for (int c = 0; c < 16; c++)
                    acc[r][c] = fmaf(a[r], kb[c], acc[r][c]);
        }
        __syncthreads();
    }

    // mask + relu^2, write to global
    const bool prevok = (wblk > 0);
    float* ow = attnw + (size_t)blk * WSZ * 256;
    #pragma unroll
    for (int r = 0; r < 8; r++) {
        int i = ty + (r << 4);
        #pragma unroll
        for (int c = 0; c < 16; c++) {
            int j = tx + (c << 4);
            // keep <=> t_j valid and i <= j <= i+128  (window = W+1 keys, causal)
            bool keep = (j >= i) && (j <= i + WSZ) && (prevok || j >= WSZ);
            float s = acc[r][c];
            float av = (keep && s > 0.f) ? s * s : 0.f;
            ow[i * 256 + j] = av;
        }
    }
}

// ---------------------------------------------------------------------------
// attn_out: out_blk[128, 128cols] = attn[128,256] @ v2[256, n0:n0+128]
// grid = (DIM/128, NBLK)
// ---------------------------------------------------------------------------
__global__ __launch_bounds__(256) void attn_out_kernel(
    const float* __restrict__ qkv, const float* __restrict__ attnw,
    float* __restrict__ out)
{
    __shared__ float Ws[16][129];
    __shared__ float Vs[16][132];
    const int tid = threadIdx.x;
    const int ty = tid >> 4, tx = tid & 15;
    const int blk = blockIdx.y;
    const int n0 = blockIdx.x << 7;
    const int b = blk >> 6, wblk = blk & 63;
    const int qbase = b * TT + wblk * WSZ;
    const int kbase = qbase - WSZ;
    const int bstart = b * TT;
    const float* aw = attnw + (size_t)blk * WSZ * 256;

    float acc[8][8];
    #pragma unroll
    for (int r = 0; r < 8; r++)
        #pragma unroll
        for (int c = 0; c < 8; c++) acc[r][c] = 0.f;

    for (int j0 = 0; j0 < 256; j0 += 16) {
        // attn tile: 128 rows x 16 j, transposed into Ws[j][m]
        #pragma unroll
        for (int i = 0; i < 2; i++) {
            int idx = tid + (i << 8);
            int row = idx >> 2;
            int kc  = (idx & 3) << 2;
            float4 v = *(const float4*)(aw + (size_t)row * 256 + j0 + kc);
            Ws[kc+0][row] = v.x; Ws[kc+1][row] = v.y;
            Ws[kc+2][row] = v.z; Ws[kc+3][row] = v.w;
        }
        // V tile: 16 key rows x 128 cols, guard prev block
        #pragma unroll
        for (int i = 0; i < 2; i++) {
            int idx = tid + (i << 8);
            int row = idx >> 5;          // 32 float4 per row
            int nc  = (idx & 31) << 2;
            int gr = kbase + j0 + row;
            float4 v = make_float4(0.f, 0.f, 0.f, 0.f);
            if (gr >= bstart)
                v = *(const float4*)(qkv + (size_t)gr * TDIM + 2 * DIM + n0 + nc);
            *(float4*)(&Vs[row][nc]) = v;
        }
        __syncthreads();
        #pragma unroll
        for (int kk = 0; kk < 16; kk++) {
            float a[8], bv[8];
            #pragma unroll
            for (int r = 0; r < 8; r++) a[r] = Ws[kk][ty + (r << 4)];
            #pragma unroll
            for (int c = 0; c < 8; c++) bv[c] = Vs[kk][tx + (c << 4)];
            #pragma unroll
            for (int r = 0; r < 8; r++)
                #pragma unroll
                for (int c = 0; c < 8; c++)
                    acc[r][c] = fmaf(a[r], bv[c], acc[r][c]);
        }
        __syncthreads();
    }

    #pragma unroll
    for (int r = 0; r < 8; r++) {
        int m = qbase + ty + (r << 4);
        #pragma unroll
        for (int c = 0; c < 8; c++)
            out[(size_t)m * DIM + n0 + tx + (c << 4)] = acc[r][c];
    }
}

// ---------------------------------------------------------------------------
extern "C" void kernel_launch(void* const* d_in, const int* in_sizes, int n_in,
                              void* d_out, int out_size)
{
    (void)in_sizes; (void)n_in; (void)out_size;
    const float* x      = (const float*)d_in[0];  // [B,T,D]
    const float* w_attn = (const float*)d_in[1];  // [3D, D]
    const float* w_o    = (const float*)d_in[2];  // [D, D]
    float* out = (float*)d_out;

    float *qkv, *attnw, *att;
    cudaGetSymbolAddress((void**)&qkv,   g_qkv);
    cudaGetSymbolAddress((void**)&attnw, g_attnw);
    cudaGetSymbolAddress((void**)&att,   g_att);

    // 1) qkv = x @ w_attn^T  (q columns scaled by 1/W)
    sgemm_abt<<<dim3(TDIM / 128, MROWS / 128), 256>>>(
        x, w_attn, qkv, MROWS, TDIM, DIM, DIM, 1.0f / (float)WSZ);

    // 2) attention weights (mask + relu^2)
    attn_sim_kernel<<<NBLK, 256>>>(qkv, attnw);

    // 3) attn @ v
    attn_out_kernel<<<dim3(DIM / 128, NBLK), 256>>>(qkv, attnw, att);

    // 4) out = att @ w_o^T
    sgemm_abt<<<dim3(DIM / 128, MROWS / 128), 256>>>(
        att, w_o, out, MROWS, DIM, DIM, 0, 1.0f);
}

// round 3
// speedup vs baseline: 3.3931x; 3.3931x over previous
#include <cuda_runtime.h>
#include <cuda_bf16.h>
#include <cstdint>
#include <cstddef>

#define DIM   2048
#define TDIM  6144
#define BB    2
#define TT    8192
#define MROWS (BB*TT)
#define WSZ   128
#define NBLK  (MROWS/WSZ)

// ---------------- scratch (static device globals) ----------------
__device__ float g_qkv[(size_t)MROWS * TDIM];          // fp32 [q|k|v]
__device__ float g_attnw[(size_t)NBLK * WSZ * 256];    // relu^2 weights
__device__ __nv_bfloat16 g_xh[(size_t)MROWS * DIM];
__device__ __nv_bfloat16 g_xl[(size_t)MROWS * DIM];
__device__ __nv_bfloat16 g_wah[(size_t)TDIM * DIM];
__device__ __nv_bfloat16 g_wal[(size_t)TDIM * DIM];
__device__ __nv_bfloat16 g_woh[(size_t)DIM * DIM];
__device__ __nv_bfloat16 g_wol[(size_t)DIM * DIM];
__device__ __nv_bfloat16 g_ath[(size_t)MROWS * DIM];
__device__ __nv_bfloat16 g_atl[(size_t)MROWS * DIM];

// ---------------- helpers ----------------
__device__ __forceinline__ uint32_t smem_u32(const void* p) {
    uint32_t a;
    asm("{ .reg .u64 t; cvta.to.shared.u64 t, %1; cvt.u32.u64 %0, t; }" : "=r"(a) : "l"(p));
    return a;
}
#define SWZ128(o) ((o) ^ (((o) >> 3) & 0x70))

#define LDSM_X4(r, a) \
    asm volatile("ldmatrix.sync.aligned.m8n8.x4.shared.b16 {%0,%1,%2,%3}, [%4];" \
        : "=r"((r)[0]), "=r"((r)[1]), "=r"((r)[2]), "=r"((r)[3]) : "r"(a))

__device__ __forceinline__ void mma16816(float* d, const uint32_t* a, const uint32_t* b) {
    asm volatile("mma.sync.aligned.m16n8k16.row.col.f32.bf16.bf16.f32 "
        "{%0,%1,%2,%3}, {%4,%5,%6,%7}, {%8,%9}, {%0,%1,%2,%3};"
        : "+f"(d[0]), "+f"(d[1]), "+f"(d[2]), "+f"(d[3])
        : "r"(a[0]), "r"(a[1]), "r"(a[2]), "r"(a[3]), "r"(b[0]), "r"(b[1]));
}

// ---------------- fp32 -> (hi,lo) bf16 split ----------------
__global__ __launch_bounds__(256) void split_kernel(
    const float* __restrict__ src, __nv_bfloat16* __restrict__ hi,
    __nv_bfloat16* __restrict__ lo, int n4)
{
    int i = blockIdx.x * blockDim.x + threadIdx.x;
    if (i >= n4) return;
    float4 v = ((const float4*)src)[i];
    float vv[4] = {v.x, v.y, v.z, v.w};
    __nv_bfloat16 h4[4], l4[4];
    #pragma unroll
    for (int j = 0; j < 4; j++) {
        __nv_bfloat16 h = __float2bfloat16(vv[j]);
        h4[j] = h;
        l4[j] = __float2bfloat16(vv[j] - __bfloat162float(h));
    }
    ((uint2*)hi)[i] = *(uint2*)h4;
    ((uint2*)lo)[i] = *(uint2*)l4;
}

// ---------------- split-bf16 HMMA GEMM: C[M,N] = A[M,K] @ B[N,K]^T ----------------
// 128x128 CTA tile, K-chunk 64, 2-stage cp.async double buffer,
// 8 warps (64x32 each), mma.sync m16n8k16, 3 passes (hh+hl+lh).
#define TILE_B   16384              // 128 rows x 128 bytes (64 bf16)
#define STAGE_B  (4*TILE_B)         // Ah, Al, Bh, Bl
#define GEMM_SMEM (2*STAGE_B + 1024)

__global__ __launch_bounds__(256, 1) void gemm_hmma(
    const __nv_bfloat16* __restrict__ Ahg, const __nv_bfloat16* __restrict__ Alg,
    const __nv_bfloat16* __restrict__ Bhg, const __nv_bfloat16* __restrict__ Blg,
    float* __restrict__ C, int M, int N, int K, int scale_cols, float scale)
{
    extern __shared__ char smem[];
    const uint32_t tiles = (smem_u32(smem) + 1023) & ~1023u;
    const int tid = threadIdx.x, wid = tid >> 5, lane = tid & 31;
    const int m0 = blockIdx.y << 7, n0 = blockIdx.x << 7;
    const int wm = (wid & 1) << 6, wn = (wid >> 1) << 5;

    const __nv_bfloat16* Ah = Ahg + (size_t)m0 * K;
    const __nv_bfloat16* Al = Alg + (size_t)m0 * K;
    const __nv_bfloat16* Bh = Bhg + (size_t)n0 * K;
    const __nv_bfloat16* Bl = Blg + (size_t)n0 * K;

    float acc[4][4][4];
    #pragma unroll
    for (int a = 0; a < 4; a++)
        #pragma unroll
        for (int b = 0; b < 4; b++)
            #pragma unroll
            for (int c = 0; c < 4; c++) acc[a][b][c] = 0.f;

    // lane-invariant ldmatrix sub-offsets
    const int mat = lane >> 3, lr = lane & 7;
    const int rA = ((mat & 1) << 3) + lr, cA = (mat >> 1) << 4;   // A: row-halves, k-halves
    const int rB = ((mat >> 1) << 3) + lr, cB = (mat & 1) << 4;   // B: n-halves,  k-halves

    auto load_stage = [&](int st, int k0) {
        const uint32_t base = tiles + st * STAGE_B;
        const __nv_bfloat16* srcs[4] = {Ah + k0, Al + k0, Bh + k0, Bl + k0};
        #pragma unroll
        for (int t = 0; t < 4; t++) {
            const uint32_t tb = base + t * TILE_B;
            const __nv_bfloat16* s = srcs[t];
            #pragma unroll
            for (int i = 0; i < 4; i++) {
                int idx = tid + (i << 8);
                int row = idx >> 3, c = idx & 7;
                uint32_t dst = tb + SWZ128(row * 128 + c * 16);
                const void* src = s + (size_t)row * K + c * 8;
                asm volatile("cp.async.cg.shared.global [%0], [%1], 16;" :: "r"(dst), "l"(src));
            }
        }
    };

    const int NS = K >> 6;
    load_stage(0, 0);
    asm volatile("cp.async.commit_group;" ::: "memory");

    for (int s = 0; s < NS; s++) {
        const int buf = s & 1;
        if (s + 1 < NS) {
            load_stage(buf ^ 1, (s + 1) * 64);
            asm volatile("cp.async.commit_group;" ::: "memory");
            asm volatile("cp.async.wait_group 1;" ::: "memory");
        } else {
            asm volatile("cp.async.wait_group 0;" ::: "memory");
        }
        __syncthreads();

        const uint32_t sAh = tiles + buf * STAGE_B;
        const uint32_t sAl = sAh + TILE_B;
        const uint32_t sBh = sAh + 2 * TILE_B;
        const uint32_t sBl = sAh + 3 * TILE_B;

        #pragma unroll
        for (int k16 = 0; k16 < 4; k16++) {
            uint32_t ah[4][4], al[4][4], bh[4][2], bl[4][2];
            #pragma unroll
            for (int tm = 0; tm < 4; tm++) {
                uint32_t off = SWZ128((uint32_t)((wm + tm * 16 + rA) * 128 + cA + k16 * 32));
                LDSM_X4(ah[tm], sAh + off);
                LDSM_X4(al[tm], sAl + off);
            }
            #pragma unroll
            for (int p = 0; p < 2; p++) {
                uint32_t off = SWZ128((uint32_t)((wn + p * 16 + rB) * 128 + cB + k16 * 32));
                uint32_t t[4];
                LDSM_X4(t, sBh + off);
                bh[2*p][0] = t[0]; bh[2*p][1] = t[1];
                bh[2*p+1][0] = t[2]; bh[2*p+1][1] = t[3];
                LDSM_X4(t, sBl + off);
                bl[2*p][0] = t[0]; bl[2*p][1] = t[1];
                bl[2*p+1][0] = t[2]; bl[2*p+1][1] = t[3];
            }
            #pragma unroll
            for (int tm = 0; tm < 4; tm++)
                #pragma unroll
                for (int tn = 0; tn < 4; tn++) {
                    mma16816(acc[tm][tn], ah[tm], bh[tn]);
                    mma16816(acc[tm][tn], ah[tm], bl[tn]);
                    mma16816(acc[tm][tn], al[tm], bh[tn]);
                }
        }
        __syncthreads();
    }

    // epilogue
    const int lr4 = lane >> 2, lc2 = (lane & 3) << 1;
    #pragma unroll
    for (int tm = 0; tm < 4; tm++)
        #pragma unroll
        for (int tn = 0; tn < 4; tn++) {
            int gr = m0 + wm + tm * 16 + lr4;
            int gc = n0 + wn + tn * 8 + lc2;
            float sc = (gc < scale_cols) ? scale : 1.0f;
            float* c0 = C + (size_t)gr * N + gc;
            c0[0] = acc[tm][tn][0] * sc;
            c0[1] = acc[tm][tn][1] * sc;
            float* c1 = c0 + 8 * (size_t)N;
            c1[0] = acc[tm][tn][2] * sc;
            c1[1] = acc[tm][tn][3] * sc;
        }
}

// ---------------- attention: sim + relu^2 (fp32) ----------------
__global__ __launch_bounds__(256) void attn_sim_kernel(
    const float* __restrict__ qkv, float* __restrict__ attnw)
{
    __shared__ float Qs[16][129];
    __shared__ float Ks[16][257];
    const int tid = threadIdx.x;
    const int ty = tid >> 4, tx = tid & 15;
    const int blk = blockIdx.x;
    const int b = blk >> 6, wblk = blk & 63;
    const int qbase = b * TT + wblk * WSZ;
    const int kbase = qbase - WSZ;
    const int bstart = b * TT;

    float acc[8][16];
    #pragma unroll
    for (int r = 0; r < 8; r++)
        #pragma unroll
        for (int c = 0; c < 16; c++) acc[r][c] = 0.f;

    for (int k0 = 0; k0 < DIM; k0 += 16) {
        #pragma unroll
        for (int i = 0; i < 2; i++) {
            int idx = tid + (i << 8);
            int row = idx >> 2, kc = (idx & 3) << 2;
            float4 v = *(const float4*)(qkv + (size_t)(qbase + row) * TDIM + k0 + kc);
            Qs[kc+0][row] = v.x; Qs[kc+1][row] = v.y;
            Qs[kc+2][row] = v.z; Qs[kc+3][row] = v.w;
        }
        #pragma unroll
        for (int i = 0; i < 4; i++) {
            int idx = tid + (i << 8);
            int row = idx >> 2, kc = (idx & 3) << 2;
            int gr = kbase + row;
            float4 v = make_float4(0.f, 0.f, 0.f, 0.f);
            if (gr >= bstart)
                v = *(const float4*)(qkv + (size_t)gr * TDIM + DIM + k0 + kc);
            Ks[kc+0][row] = v.x; Ks[kc+1][row] = v.y;
            Ks[kc+2][row] = v.z; Ks[kc+3][row] = v.w;
        }
        __syncthreads();
        #pragma unroll
        for (int kk = 0; kk < 16; kk++) {
            float a[8], kb[16];
            #pragma unroll
            for (int r = 0; r < 8; r++) a[r] = Qs[kk][ty + (r << 4)];
            #pragma unroll
            for (int c = 0; c < 16; c++) kb[c] = Ks[kk][tx + (c << 4)];
            #pragma unroll
            for (int r = 0; r < 8; r++)
                #pragma unroll
                for (int c = 0; c < 16; c++)
                    acc[r][c] = fmaf(a[r], kb[c], acc[r][c]);
        }
        __syncthreads();
    }

    const bool prevok = (wblk > 0);
    float* ow = attnw + (size_t)blk * WSZ * 256;
    #pragma unroll
    for (int r = 0; r < 8; r++) {
        int i = ty + (r << 4);
        #pragma unroll
        for (int c = 0; c < 16; c++) {
            int j = tx + (c << 4);
            bool keep = (j >= i) && (j <= i + WSZ) && (prevok || j >= WSZ);
            float s = acc[r][c];
            ow[i * 256 + j] = (keep && s > 0.f) ? s * s : 0.f;
        }
    }
}

// ---------------- attention: attn @ v, output hi/lo bf16 ----------------
__global__ __launch_bounds__(256) void attn_out_kernel(
    const float* __restrict__ qkv, const float* __restrict__ attnw,
    __nv_bfloat16* __restrict__ oh, __nv_bfloat16* __restrict__ ol)
{
    __shared__ float Ws[16][129];
    __shared__ float Vs[16][132];
    const int tid = threadIdx.x;
    const int ty = tid >> 4, tx = tid & 15;
    const int blk = blockIdx.y;
    const int n0 = blockIdx.x << 7;
    const int b = blk >> 6, wblk = blk & 63;
    const int qbase = b * TT + wblk * WSZ;
    const int kbase = qbase - WSZ;
    const int bstart = b * TT;
    const float* aw = attnw + (size_t)blk * WSZ * 256;

    float acc[8][8];
    #pragma unroll
    for (int r = 0; r < 8; r++)
        #pragma unroll
        for (int c = 0; c < 8; c++) acc[r][c] = 0.f;

    for (int j0 = 0; j0 < 256; j0 += 16) {
        #pragma unroll
        for (int i = 0; i < 2; i++) {
            int idx = tid + (i << 8);
            int row = idx >> 2, kc = (idx & 3) << 2;
            float4 v = *(const float4*)(aw + (size_t)row * 256 + j0 + kc);
            Ws[kc+0][row] = v.x; Ws[kc+1][row] = v.y;
            Ws[kc+2][row] = v.z; Ws[kc+3][row] = v.w;
        }
        #pragma unroll
        for (int i = 0; i < 2; i++) {
            int idx = tid + (i << 8);
            int row = idx >> 5, nc = (idx & 31) << 2;
            int gr = kbase + j0 + row;
            float4 v = make_float4(0.f, 0.f, 0.f, 0.f);
            if (gr >= bstart)
                v = *(const float4*)(qkv + (size_t)gr * TDIM + 2 * DIM + n0 + nc);
            *(float4*)(&Vs[row][nc]) = v;
        }
        __syncthreads();
        #pragma unroll
        for (int kk = 0; kk < 16; kk++) {
            float a[8], bv[8];
            #pragma unroll
            for (int r = 0; r < 8; r++) a[r] = Ws[kk][ty + (r << 4)];
            #pragma unroll
            for (int c = 0; c < 8; c++) bv[c] = Vs[kk][tx + (c << 4)];
            #pragma unroll
            for (int r = 0; r < 8; r++)
                #pragma unroll
                for (int c = 0; c < 8; c++)
                    acc[r][c] = fmaf(a[r], bv[c], acc[r][c]);
        }
        __syncthreads();
    }

    #pragma unroll
    for (int r = 0; r < 8; r++) {
        int m = qbase + ty + (r << 4);
        #pragma unroll
        for (int c = 0; c < 8; c++) {
            size_t idx = (size_t)m * DIM + n0 + tx + (c << 4);
            float v = acc[r][c];
            __nv_bfloat16 h = __float2bfloat16(v);
            oh[idx] = h;
            ol[idx] = __float2bfloat16(v - __bfloat162float(h));
        }
    }
}

// ---------------------------------------------------------------------------
extern "C" void kernel_launch(void* const* d_in, const int* in_sizes, int n_in,
                              void* d_out, int out_size)
{
    (void)in_sizes; (void)n_in; (void)out_size;
    const float* x      = (const float*)d_in[0];
    const float* w_attn = (const float*)d_in[1];
    const float* w_o    = (const float*)d_in[2];
    float* out = (float*)d_out;

    float *qkv, *attnw;
    __nv_bfloat16 *xh, *xl, *wah, *wal, *woh, *wol, *ath, *atl;
    cudaGetSymbolAddress((void**)&qkv,   g_qkv);
    cudaGetSymbolAddress((void**)&attnw, g_attnw);
    cudaGetSymbolAddress((void**)&xh,  g_xh);   cudaGetSymbolAddress((void**)&xl,  g_xl);
    cudaGetSymbolAddress((void**)&wah, g_wah);  cudaGetSymbolAddress((void**)&wal, g_wal);
    cudaGetSymbolAddress((void**)&woh, g_woh);  cudaGetSymbolAddress((void**)&wol, g_wol);
    cudaGetSymbolAddress((void**)&ath, g_ath);  cudaGetSymbolAddress((void**)&atl, g_atl);

    cudaFuncSetAttribute(gemm_hmma,
                         cudaFuncAttributeMaxDynamicSharedMemorySize, GEMM_SMEM);

    // 0) hi/lo splits
    {
        int n4 = MROWS * DIM / 4;
        split_kernel<<<(n4 + 255) / 256, 256>>>(x, xh, xl, n4);
        n4 = TDIM * DIM / 4;
        split_kernel<<<(n4 + 255) / 256, 256>>>(w_attn, wah, wal, n4);
        n4 = DIM * DIM / 4;
        split_kernel<<<(n4 + 255) / 256, 256>>>(w_o, woh, wol, n4);
    }

    // 1) qkv = x @ w_attn^T   (q columns scaled by 1/W)
    gemm_hmma<<<dim3(TDIM / 128, MROWS / 128), 256, GEMM_SMEM>>>(
        xh, xl, wah, wal, qkv, MROWS, TDIM, DIM, DIM, 1.0f / (float)WSZ);

    // 2) attention weights
    attn_sim_kernel<<<NBLK, 256>>>(qkv, attnw);

    // 3) attn @ v -> hi/lo bf16
    attn_out_kernel<<<dim3(DIM / 128, NBLK), 256>>>(qkv, attnw, ath, atl);

    // 4) out = att @ w_o^T
    gemm_hmma<<<dim3(DIM / 128, MROWS / 128), 256, GEMM_SMEM>>>(
        ath, atl, woh, wol, out, MROWS, DIM, DIM, 0, 1.0f);
}

// round 4
// speedup vs baseline: 4.4054x; 1.2984x over previous
#include <cuda_runtime.h>
#include <cuda_fp16.h>
#include <cstdint>
#include <cstddef>

#define DIM   2048
#define TDIM  6144
#define BB    2
#define TT    8192
#define MROWS (BB*TT)
#define WSZ   128
#define NBLK  (MROWS/WSZ)

// ---------------- scratch (static device globals) ----------------
__device__ float g_qkv[(size_t)MROWS * TDIM];          // fp32 [q|k|v]
__device__ float g_attnw[(size_t)NBLK * WSZ * 256];    // relu^2 weights
__device__ __half g_xh[(size_t)MROWS * DIM];
__device__ __half g_xl[(size_t)MROWS * DIM];
__device__ __half g_wah[(size_t)TDIM * DIM];
__device__ __half g_woh[(size_t)DIM * DIM];
__device__ __half g_ath[(size_t)MROWS * DIM];
__device__ __half g_atl[(size_t)MROWS * DIM];

// ---------------- helpers ----------------
__device__ __forceinline__ uint32_t smem_u32(const void* p) {
    uint32_t a;
    asm("{ .reg .u64 t; cvta.to.shared.u64 t, %1; cvt.u32.u64 %0, t; }" : "=r"(a) : "l"(p));
    return a;
}
#define SWZ128(o) ((o) ^ (((o) >> 3) & 0x70))

#define LDSM_X4(r, a) \
    asm volatile("ldmatrix.sync.aligned.m8n8.x4.shared.b16 {%0,%1,%2,%3}, [%4];" \
        : "=r"((r)[0]), "=r"((r)[1]), "=r"((r)[2]), "=r"((r)[3]) : "r"(a))

__device__ __forceinline__ void mma16816(float* d, const uint32_t* a, const uint32_t* b) {
    asm volatile("mma.sync.aligned.m16n8k16.row.col.f32.f16.f16.f32 "
        "{%0,%1,%2,%3}, {%4,%5,%6,%7}, {%8,%9}, {%0,%1,%2,%3};"
        : "+f"(d[0]), "+f"(d[1]), "+f"(d[2]), "+f"(d[3])
        : "r"(a[0]), "r"(a[1]), "r"(a[2]), "r"(a[3]), "r"(b[0]), "r"(b[1]));
}

// ---------------- fp32 -> (hi,lo) fp16 split ----------------
__global__ __launch_bounds__(256) void split_hl_kernel(
    const float* __restrict__ src, __half* __restrict__ hi,
    __half* __restrict__ lo, int n4)
{
    int i = blockIdx.x * blockDim.x + threadIdx.x;
    if (i >= n4) return;
    float4 v = ((const float4*)src)[i];
    float vv[4] = {v.x, v.y, v.z, v.w};
    __half h4[4], l4[4];
    #pragma unroll
    for (int j = 0; j < 4; j++) {
        __half h = __float2half_rn(vv[j]);
        h4[j] = h;
        l4[j] = __float2half_rn(vv[j] - __half2float(h));
    }
    ((uint2*)hi)[i] = *(uint2*)h4;
    ((uint2*)lo)[i] = *(uint2*)l4;
}

__global__ __launch_bounds__(256) void split_h_kernel(
    const float* __restrict__ src, __half* __restrict__ hi, int n4)
{
    int i = blockIdx.x * blockDim.x + threadIdx.x;
    if (i >= n4) return;
    float4 v = ((const float4*)src)[i];
    float vv[4] = {v.x, v.y, v.z, v.w};
    __half h4[4];
    #pragma unroll
    for (int j = 0; j < 4; j++) h4[j] = __float2half_rn(vv[j]);
    ((uint2*)hi)[i] = *(uint2*)h4;
}

// ---------------- split-fp16 HMMA GEMM: C[M,N] = A[M,K] @ B[N,K]^T ----------------
// 128x128 CTA tile, K-chunk 64, 3-stage cp.async pipeline,
// 8 warps (64x32 each), mma.sync m16n8k16, 2 passes: ah*bh + al*bh.
#define TILE_B   16384              // 128 rows x 128 bytes (64 fp16)
#define STAGE_B  (3*TILE_B)         // Ah, Al, Bh
#define NSTG     3
#define GEMM_SMEM (NSTG*STAGE_B + 1024)

__global__ __launch_bounds__(256, 1) void gemm_hmma(
    const __half* __restrict__ Ahg, const __half* __restrict__ Alg,
    const __half* __restrict__ Bhg,
    float* __restrict__ C, int M, int N, int K, int scale_cols, float scale)
{
    extern __shared__ char smem[];
    const uint32_t tiles = (smem_u32(smem) + 1023) & ~1023u;
    const int tid = threadIdx.x, wid = tid >> 5, lane = tid & 31;
    const int m0 = blockIdx.y << 7, n0 = blockIdx.x << 7;
    const int wm = (wid & 1) << 6, wn = (wid >> 1) << 5;

    const __half* Ah = Ahg + (size_t)m0 * K;
    const __half* Al = Alg + (size_t)m0 * K;
    const __half* Bh = Bhg + (size_t)n0 * K;

    float acc[4][4][4];
    #pragma unroll
    for (int a = 0; a < 4; a++)
        #pragma unroll
        for (int b = 0; b < 4; b++)
            #pragma unroll
            for (int c = 0; c < 4; c++) acc[a][b][c] = 0.f;

    const int mat = lane >> 3, lr = lane & 7;
    const int rA = ((mat & 1) << 3) + lr, cA = (mat >> 1) << 4;
    const int rB = ((mat >> 1) << 3) + lr, cB = (mat & 1) << 4;

    auto load_stage = [&](int st, int k0) {
        const uint32_t base = tiles + st * STAGE_B;
        const __half* srcs[3] = {Ah + k0, Al + k0, Bh + k0};
        #pragma unroll
        for (int t = 0; t < 3; t++) {
            const uint32_t tb = base + t * TILE_B;
            const __half* s = srcs[t];
            #pragma unroll
            for (int i = 0; i < 4; i++) {
                int idx = tid + (i << 8);
                int row = idx >> 3, c = idx & 7;
                uint32_t dst = tb + SWZ128(row * 128 + c * 16);
                const void* src = s + (size_t)row * K + c * 8;
                asm volatile("cp.async.cg.shared.global [%0], [%1], 16;" :: "r"(dst), "l"(src));
            }
        }
    };

    const int NS = K >> 6;      // 32
    load_stage(0, 0);
    asm volatile("cp.async.commit_group;" ::: "memory");
    load_stage(1, 64);
    asm volatile("cp.async.commit_group;" ::: "memory");

    int sidx = 0;
    for (int s = 0; s < NS; s++) {
        asm volatile("cp.async.wait_group 1;" ::: "memory");
        __syncthreads();

        if (s + 2 < NS) {
            int nst = sidx + 2; if (nst >= NSTG) nst -= NSTG;
            load_stage(nst, (s + 2) * 64);
            asm volatile("cp.async.commit_group;" ::: "memory");
        }

        const uint32_t sAh = tiles + sidx * STAGE_B;
        const uint32_t sAl = sAh + TILE_B;
        const uint32_t sBh = sAh + 2 * TILE_B;

        #pragma unroll
        for (int k16 = 0; k16 < 4; k16++) {
            uint32_t ah[4][4], al[4][4], bh[4][2];
            #pragma unroll
            for (int tm = 0; tm < 4; tm++) {
                uint32_t off = SWZ128((uint32_t)((wm + tm * 16 + rA) * 128 + cA + k16 * 32));
                LDSM_X4(ah[tm], sAh + off);
                LDSM_X4(al[tm], sAl + off);
            }
            #pragma unroll
            for (int p = 0; p < 2; p++) {
                uint32_t off = SWZ128((uint32_t)((wn + p * 16 + rB) * 128 + cB + k16 * 32));
                uint32_t t[4];
                LDSM_X4(t, sBh + off);
                bh[2*p][0] = t[0]; bh[2*p][1] = t[1];
                bh[2*p+1][0] = t[2]; bh[2*p+1][1] = t[3];
            }
            #pragma unroll
            for (int tm = 0; tm < 4; tm++)
                #pragma unroll
                for (int tn = 0; tn < 4; tn++) {
                    mma16816(acc[tm][tn], ah[tm], bh[tn]);
                    mma16816(acc[tm][tn], al[tm], bh[tn]);
                }
        }
        if (++sidx == NSTG) sidx = 0;
        __syncthreads();
    }

    // epilogue
    const int lr4 = lane >> 2, lc2 = (lane & 3) << 1;
    #pragma unroll
    for (int tm = 0; tm < 4; tm++)
        #pragma unroll
        for (int tn = 0; tn < 4; tn++) {
            int gr = m0 + wm + tm * 16 + lr4;
            int gc = n0 + wn + tn * 8 + lc2;
            float sc = (gc < scale_cols) ? scale : 1.0f;
            float* c0 = C + (size_t)gr * N + gc;
            c0[0] = acc[tm][tn][0] * sc;
            c0[1] = acc[tm][tn][1] * sc;
            float* c1 = c0 + 8 * (size_t)N;
            c1[0] = acc[tm][tn][2] * sc;
            c1[1] = acc[tm][tn][3] * sc;
        }
}

// ---------------- attention: sim + relu^2 (fp32) ----------------
__global__ __launch_bounds__(256) void attn_sim_kernel(
    const float* __restrict__ qkv, float* __restrict__ attnw)
{
    __shared__ float Qs[16][129];
    __shared__ float Ks[16][257];
    const int tid = threadIdx.x;
    const int ty = tid >> 4, tx = tid & 15;
    const int blk = blockIdx.x;
    const int b = blk >> 6, wblk = blk & 63;
    const int qbase = b * TT + wblk * WSZ;
    const int kbase = qbase - WSZ;
    const int bstart = b * TT;

    float acc[8][16];
    #pragma unroll
    for (int r = 0; r < 8; r++)
        #pragma unroll
        for (int c = 0; c < 16; c++) acc[r][c] = 0.f;

    for (int k0 = 0; k0 < DIM; k0 += 16) {
        #pragma unroll
        for (int i = 0; i < 2; i++) {
            int idx = tid + (i << 8);
            int row = idx >> 2, kc = (idx & 3) << 2;
            float4 v = *(const float4*)(qkv + (size_t)(qbase + row) * TDIM + k0 + kc);
            Qs[kc+0][row] = v.x; Qs[kc+1][row] = v.y;
            Qs[kc+2][row] = v.z; Qs[kc+3][row] = v.w;
        }
        #pragma unroll
        for (int i = 0; i < 4; i++) {
            int idx = tid + (i << 8);
            int row = idx >> 2, kc = (idx & 3) << 2;
            int gr = kbase + row;
            float4 v = make_float4(0.f, 0.f, 0.f, 0.f);
            if (gr >= bstart)
                v = *(const float4*)(qkv + (size_t)gr * TDIM + DIM + k0 + kc);
            Ks[kc+0][row] = v.x; Ks[kc+1][row] = v.y;
            Ks[kc+2][row] = v.z; Ks[kc+3][row] = v.w;
        }
        __syncthreads();
        #pragma unroll
        for (int kk = 0; kk < 16; kk++) {
            float a[8], kb[16];
            #pragma unroll
            for (int r = 0; r < 8; r++) a[r] = Qs[kk][ty + (r << 4)];
            #pragma unroll
            for (int c = 0; c < 16; c++) kb[c] = Ks[kk][tx + (c << 4)];
            #pragma unroll
            for (int r = 0; r < 8; r++)
                #pragma unroll
                for (int c = 0; c < 16; c++)
                    acc[r][c] = fmaf(a[r], kb[c], acc[r][c]);
        }
        __syncthreads();
    }

    const bool prevok = (wblk > 0);
    float* ow = attnw + (size_t)blk * WSZ * 256;
    #pragma unroll
    for (int r = 0; r < 8; r++) {
        int i = ty + (r << 4);
        #pragma unroll
        for (int c = 0; c < 16; c++) {
            int j = tx + (c << 4);
            bool keep = (j >= i) && (j <= i + WSZ) && (prevok || j >= WSZ);
            float s = acc[r][c];
            ow[i * 256 + j] = (keep && s > 0.f) ? s * s : 0.f;
        }
    }
}

// ---------------- attention: attn @ v, output hi/lo fp16 ----------------
__global__ __launch_bounds__(256) void attn_out_kernel(
    const float* __restrict__ qkv, const float* __restrict__ attnw,
    __half* __restrict__ oh, __half* __restrict__ ol)
{
    __shared__ float Ws[16][129];
    __shared__ float Vs[16][132];
    const int tid = threadIdx.x;
    const int ty = tid >> 4, tx = tid & 15;
    const int blk = blockIdx.y;
    const int n0 = blockIdx.x << 7;
    const int b = blk >> 6, wblk = blk & 63;
    const int qbase = b * TT + wblk * WSZ;
    const int kbase = qbase - WSZ;
    const int bstart = b * TT;
    const float* aw = attnw + (size_t)blk * WSZ * 256;

    float acc[8][8];
    #pragma unroll
    for (int r = 0; r < 8; r++)
        #pragma unroll
        for (int c = 0; c < 8; c++) acc[r][c] = 0.f;

    for (int j0 = 0; j0 < 256; j0 += 16) {
        #pragma unroll
        for (int i = 0; i < 2; i++) {
            int idx = tid + (i << 8);
            int row = idx >> 2, kc = (idx & 3) << 2;
            float4 v = *(const float4*)(aw + (size_t)row * 256 + j0 + kc);
            Ws[kc+0][row] = v.x; Ws[kc+1][row] = v.y;
            Ws[kc+2][row] = v.z; Ws[kc+3][row] = v.w;
        }
        #pragma unroll
        for (int i = 0; i < 2; i++) {
            int idx = tid + (i << 8);
            int row = idx >> 5, nc = (idx & 31) << 2;
            int gr = kbase + j0 + row;
            float4 v = make_float4(0.f, 0.f, 0.f, 0.f);
            if (gr >= bstart)
                v = *(const float4*)(qkv + (size_t)gr * TDIM + 2 * DIM + n0 + nc);
            *(float4*)(&Vs[row][nc]) = v;
        }
        __syncthreads();
        #pragma unroll
        for (int kk = 0; kk < 16; kk++) {
            float a[8], bv[8];
            #pragma unroll
            for (int r = 0; r < 8; r++) a[r] = Ws[kk][ty + (r << 4)];
            #pragma unroll
            for (int c = 0; c < 8; c++) bv[c] = Vs[kk][tx + (c << 4)];
            #pragma unroll
            for (int r = 0; r < 8; r++)
                #pragma unroll
                for (int c = 0; c < 8; c++)
                    acc[r][c] = fmaf(a[r], bv[c], acc[r][c]);
        }
        __syncthreads();
    }

    #pragma unroll
    for (int r = 0; r < 8; r++) {
        int m = qbase + ty + (r << 4);
        #pragma unroll
        for (int c = 0; c < 8; c++) {
            size_t idx = (size_t)m * DIM + n0 + tx + (c << 4);
            float v = acc[r][c];
            __half h = __float2half_rn(v);
            oh[idx] = h;
            ol[idx] = __float2half_rn(v - __half2float(h));
        }
    }
}

// ---------------------------------------------------------------------------
extern "C" void kernel_launch(void* const* d_in, const int* in_sizes, int n_in,
                              void* d_out, int out_size)
{
    (void)in_sizes; (void)n_in; (void)out_size;
    const float* x      = (const float*)d_in[0];
    const float* w_attn = (const float*)d_in[1];
    const float* w_o    = (const float*)d_in[2];
    float* out = (float*)d_out;

    float *qkv, *attnw;
    __half *xh, *xl, *wah, *woh, *ath, *atl;
    cudaGetSymbolAddress((void**)&qkv,   g_qkv);
    cudaGetSymbolAddress((void**)&attnw, g_attnw);
    cudaGetSymbolAddress((void**)&xh,  g_xh);   cudaGetSymbolAddress((void**)&xl,  g_xl);
    cudaGetSymbolAddress((void**)&wah, g_wah);
    cudaGetSymbolAddress((void**)&woh, g_woh);
    cudaGetSymbolAddress((void**)&ath, g_ath);  cudaGetSymbolAddress((void**)&atl, g_atl);

    cudaFuncSetAttribute(gemm_hmma,
                         cudaFuncAttributeMaxDynamicSharedMemorySize, GEMM_SMEM);

    // 0) fp16 splits: x -> hi/lo, weights -> hi only
    {
        int n4 = MROWS * DIM / 4;
        split_hl_kernel<<<(n4 + 255) / 256, 256>>>(x, xh, xl, n4);
        n4 = TDIM * DIM / 4;
        split_h_kernel<<<(n4 + 255) / 256, 256>>>(w_attn, wah, n4);
        n4 = DIM * DIM / 4;
        split_h_kernel<<<(n4 + 255) / 256, 256>>>(w_o, woh, n4);
    }

    // 1) qkv = x @ w_attn^T   (q columns scaled by 1/W)
    gemm_hmma<<<dim3(TDIM / 128, MROWS / 128), 256, GEMM_SMEM>>>(
        xh, xl, wah, qkv, MROWS, TDIM, DIM, DIM, 1.0f / (float)WSZ);

    // 2) attention weights
    attn_sim_kernel<<<NBLK, 256>>>(qkv, attnw);

    // 3) attn @ v -> hi/lo fp16
    attn_out_kernel<<<dim3(DIM / 128, NBLK), 256>>>(qkv, attnw, ath, atl);

    // 4) out = att @ w_o^T
    gemm_hmma<<<dim3(DIM / 128, MROWS / 128), 256, GEMM_SMEM>>>(
        ath, atl, woh, out, MROWS, DIM, DIM, 0, 1.0f);
}

// round 6
// speedup vs baseline: 5.1027x; 1.1583x over previous
#include <cuda_runtime.h>
#include <cuda_fp16.h>
#include <cstdint>
#include <cstddef>

#define DIM   2048
#define TDIM  6144
#define BB    2
#define TT    8192
#define MROWS (BB*TT)
#define WSZ   128
#define NBLK  (MROWS/WSZ)

// ---------------- scratch (static device globals) ----------------
__device__ __half g_xh[(size_t)MROWS * DIM];
__device__ __half g_xl[(size_t)MROWS * DIM];
__device__ __half g_wah[(size_t)TDIM * DIM];
__device__ __half g_woh[(size_t)DIM * DIM];
__device__ __half g_qkvh[(size_t)MROWS * TDIM];
__device__ __half g_qkvl[(size_t)MROWS * TDIM];
__device__ __half g_awh[(size_t)NBLK * WSZ * 256];
__device__ __half g_awl[(size_t)NBLK * WSZ * 256];
__device__ __half g_ath[(size_t)MROWS * DIM];
__device__ __half g_atl[(size_t)MROWS * DIM];

// ---------------- helpers ----------------
__device__ __forceinline__ uint32_t smem_u32(const void* p) {
    uint32_t a;
    asm("{ .reg .u64 t; cvta.to.shared.u64 t, %1; cvt.u32.u64 %0, t; }" : "=r"(a) : "l"(p));
    return a;
}
#define SWZ128(o) ((o) ^ (((o) >> 3) & 0x70))

#define LDSM_X4(r, a) \
    asm volatile("ldmatrix.sync.aligned.m8n8.x4.shared.b16 {%0,%1,%2,%3}, [%4];" \
        : "=r"((r)[0]), "=r"((r)[1]), "=r"((r)[2]), "=r"((r)[3]) : "r"(a))
#define LDSM_X4_T(r, a) \
    asm volatile("ldmatrix.sync.aligned.m8n8.x4.trans.shared.b16 {%0,%1,%2,%3}, [%4];" \
        : "=r"((r)[0]), "=r"((r)[1]), "=r"((r)[2]), "=r"((r)[3]) : "r"(a))

__device__ __forceinline__ void mma16816(float* d, const uint32_t* a, const uint32_t* b) {
    asm volatile("mma.sync.aligned.m16n8k16.row.col.f32.f16.f16.f32 "
        "{%0,%1,%2,%3}, {%4,%5,%6,%7}, {%8,%9}, {%0,%1,%2,%3};"
        : "+f"(d[0]), "+f"(d[1]), "+f"(d[2]), "+f"(d[3])
        : "r"(a[0]), "r"(a[1]), "r"(a[2]), "r"(a[3]), "r"(b[0]), "r"(b[1]));
}

#define CPA(dst, src) \
    asm volatile("cp.async.cg.shared.global [%0], [%1], 16;" :: "r"(dst), "l"(src))
#define CPA_Z(dst, src, pred) \
    asm volatile("cp.async.cg.shared.global [%0], [%1], 16, %2;" :: "r"(dst), "l"(src), "r"((pred) ? 16 : 0))
#define CP_COMMIT() asm volatile("cp.async.commit_group;" ::: "memory")
#define CP_WAIT(n)  asm volatile("cp.async.wait_group %0;" :: "n"(n) : "memory")

__device__ __forceinline__ void write_hl2(__half* H, __half* L, size_t idx, float v0, float v1) {
    __half h0 = __float2half_rn(v0), h1 = __float2half_rn(v1);
    __half l0 = __float2half_rn(v0 - __half2float(h0));
    __half l1 = __float2half_rn(v1 - __half2float(h1));
    *(__half2*)(H + idx) = __halves2half2(h0, h1);
    *(__half2*)(L + idx) = __halves2half2(l0, l1);
}

// ---------------- fp32 -> fp16 splits ----------------
__global__ __launch_bounds__(256) void split_hl_kernel(
    const float* __restrict__ src, __half* __restrict__ hi,
    __half* __restrict__ lo, int n4)
{
    int i = blockIdx.x * blockDim.x + threadIdx.x;
    if (i >= n4) return;
    float4 v = ((const float4*)src)[i];
    float vv[4] = {v.x, v.y, v.z, v.w};
    __half h4[4], l4[4];
    #pragma unroll
    for (int j = 0; j < 4; j++) {
        __half h = __float2half_rn(vv[j]);
        h4[j] = h;
        l4[j] = __float2half_rn(vv[j] - __half2float(h));
    }
    ((uint2*)hi)[i] = *(uint2*)h4;
    ((uint2*)lo)[i] = *(uint2*)l4;
}

__global__ __launch_bounds__(256) void split_h_kernel(
    const float* __restrict__ src, __half* __restrict__ hi, int n4)
{
    int i = blockIdx.x * blockDim.x + threadIdx.x;
    if (i >= n4) return;
    float4 v = ((const float4*)src)[i];
    float vv[4] = {v.x, v.y, v.z, v.w};
    __half h4[4];
    #pragma unroll
    for (int j = 0; j < 4; j++) h4[j] = __float2half_rn(vv[j]);
    ((uint2*)hi)[i] = *(uint2*)h4;
}

// ---------------- split-fp16 HMMA GEMM: C = A @ B^T ----------------
#define TILE_B   16384
#define STAGE_B  (3*TILE_B)
#define NSTG     3
#define GEMM_SMEM (NSTG*STAGE_B + 1024)

template<int OUT_HL>
__global__ __launch_bounds__(256, 1) void gemm_hmma(
    const __half* __restrict__ Ahg, const __half* __restrict__ Alg,
    const __half* __restrict__ Bhg,
    float* __restrict__ C, __half* __restrict__ Ch, __half* __restrict__ Cl,
    int M, int N, int K, int scale_cols, float scale)
{
    extern __shared__ char smem[];
    const uint32_t tiles = (smem_u32(smem) + 1023) & ~1023u;
    const int tid = threadIdx.x, wid = tid >> 5, lane = tid & 31;
    const int m0 = blockIdx.y << 7, n0 = blockIdx.x << 7;
    const int wm = (wid & 1) << 6, wn = (wid >> 1) << 5;

    const __half* Ah = Ahg + (size_t)m0 * K;
    const __half* Al = Alg + (size_t)m0 * K;
    const __half* Bh = Bhg + (size_t)n0 * K;

    float acc[4][4][4];
    #pragma unroll
    for (int a = 0; a < 4; a++)
        #pragma unroll
        for (int b = 0; b < 4; b++)
            #pragma unroll
            for (int c = 0; c < 4; c++) acc[a][b][c] = 0.f;

    const int mat = lane >> 3, lr = lane & 7;
    const int rA = ((mat & 1) << 3) + lr, cA = (mat >> 1) << 4;
    const int rB = ((mat >> 1) << 3) + lr, cB = (mat & 1) << 4;

    auto load_stage = [&](int st, int k0) {
        const uint32_t base = tiles + st * STAGE_B;
        const __half* srcs[3] = {Ah + k0, Al + k0, Bh + k0};
        #pragma unroll
        for (int t = 0; t < 3; t++) {
            const uint32_t tb = base + t * TILE_B;
            const __half* s = srcs[t];
            #pragma unroll
            for (int i = 0; i < 4; i++) {
                int idx = tid + (i << 8);
                int row = idx >> 3, c = idx & 7;
                CPA(tb + SWZ128(row * 128 + c * 16), s + (size_t)row * K + c * 8);
            }
        }
    };

    const int NS = K >> 6;
    load_stage(0, 0);
    CP_COMMIT();
    load_stage(1, 64);
    CP_COMMIT();

    int sidx = 0;
    for (int s = 0; s < NS; s++) {
        CP_WAIT(1);
        __syncthreads();
        if (s + 2 < NS) {
            int nst = sidx + 2; if (nst >= NSTG) nst -= NSTG;
            load_stage(nst, (s + 2) * 64);
            CP_COMMIT();
        }
        const uint32_t sAh = tiles + sidx * STAGE_B;
        const uint32_t sAl = sAh + TILE_B;
        const uint32_t sBh = sAh + 2 * TILE_B;

        #pragma unroll
        for (int k16 = 0; k16 < 4; k16++) {
            uint32_t ah[4][4], al[4][4], bh[4][2];
            #pragma unroll
            for (int tm = 0; tm < 4; tm++) {
                uint32_t off = SWZ128((uint32_t)((wm + tm * 16 + rA) * 128 + cA + k16 * 32));
                LDSM_X4(ah[tm], sAh + off);
                LDSM_X4(al[tm], sAl + off);
            }
            #pragma unroll
            for (int p = 0; p < 2; p++) {
                uint32_t off = SWZ128((uint32_t)((wn + p * 16 + rB) * 128 + cB + k16 * 32));
                uint32_t t[4];
                LDSM_X4(t, sBh + off);
                bh[2*p][0] = t[0]; bh[2*p][1] = t[1];
                bh[2*p+1][0] = t[2]; bh[2*p+1][1] = t[3];
            }
            #pragma unroll
            for (int tm = 0; tm < 4; tm++)
                #pragma unroll
                for (int tn = 0; tn < 4; tn++) {
                    mma16816(acc[tm][tn], ah[tm], bh[tn]);
                    mma16816(acc[tm][tn], al[tm], bh[tn]);
                }
        }
        if (++sidx == NSTG) sidx = 0;
        __syncthreads();
    }

    const int lr4 = lane >> 2, lc2 = (lane & 3) << 1;
    #pragma unroll
    for (int tm = 0; tm < 4; tm++)
        #pragma unroll
        for (int tn = 0; tn < 4; tn++) {
            int gr = m0 + wm + tm * 16 + lr4;
            int gc = n0 + wn + tn * 8 + lc2;
            float sc = (gc < scale_cols) ? scale : 1.0f;
            float v0 = acc[tm][tn][0] * sc, v1 = acc[tm][tn][1] * sc;
            float v2 = acc[tm][tn][2] * sc, v3 = acc[tm][tn][3] * sc;
            if (OUT_HL) {
                write_hl2(Ch, Cl, (size_t)gr * N + gc, v0, v1);
                write_hl2(Ch, Cl, (size_t)(gr + 8) * N + gc, v2, v3);
            } else {
                float* c0 = C + (size_t)gr * N + gc;
                c0[0] = v0; c0[1] = v1;
                float* c1 = c0 + 8 * (size_t)N;
                c1[0] = v2; c1[1] = v3;
            }
        }
}

// ---------------- attn_sim (HMMA): sim = q @ k2^T, mask, relu^2, hi/lo out ----------------
#define ASTAGE_B (4*TILE_B)
#define ASIM_SMEM (NSTG*ASTAGE_B + 1024)

__global__ __launch_bounds__(256, 1) void attn_sim_hmma(
    const __half* __restrict__ qkvh, const __half* __restrict__ qkvl,
    __half* __restrict__ awh, __half* __restrict__ awl)
{
    extern __shared__ char smem[];
    const uint32_t tiles = (smem_u32(smem) + 1023) & ~1023u;
    const int tid = threadIdx.x, wid = tid >> 5, lane = tid & 31;
    const int jhalf = blockIdx.x;
    const int blk = blockIdx.y;
    const int b = blk >> 6, wblk = blk & 63;
    const int qbase = b * TT + wblk * WSZ;
    const int krow0 = qbase - WSZ + jhalf * WSZ;
    const int bstart = b * TT;
    const int wm = (wid & 1) << 6, wn = (wid >> 1) << 5;

    float acc[4][4][4];
    #pragma unroll
    for (int a = 0; a < 4; a++)
        #pragma unroll
        for (int b2 = 0; b2 < 4; b2++)
            #pragma unroll
            for (int c = 0; c < 4; c++) acc[a][b2][c] = 0.f;

    const int mat = lane >> 3, lr = lane & 7;
    const int rA = ((mat & 1) << 3) + lr, cA = (mat >> 1) << 4;
    const int rB = ((mat >> 1) << 3) + lr, cB = (mat & 1) << 4;

    auto load_stage = [&](int st, int k0) {
        const uint32_t base = tiles + st * ASTAGE_B;
        #pragma unroll
        for (int i = 0; i < 4; i++) {
            int idx = tid + (i << 8);
            int row = idx >> 3, c = idx & 7;
            size_t qoff = (size_t)(qbase + row) * TDIM + k0 + c * 8;
            CPA(base + SWZ128(row * 128 + c * 16), qkvh + qoff);
            CPA(base + TILE_B + SWZ128(row * 128 + c * 16), qkvl + qoff);
            int grow = krow0 + row;
            bool ok = grow >= bstart;
            size_t koff = (size_t)grow * TDIM + DIM + k0 + c * 8;
            CPA_Z(base + 2 * TILE_B + SWZ128(row * 128 + c * 16), qkvh + koff, ok);
            CPA_Z(base + 3 * TILE_B + SWZ128(row * 128 + c * 16), qkvl + koff, ok);
        }
    };

    const int NS = DIM >> 6;
    load_stage(0, 0);
    CP_COMMIT();
    load_stage(1, 64);
    CP_COMMIT();

    int sidx = 0;
    for (int s = 0; s < NS; s++) {
        CP_WAIT(1);
        __syncthreads();
        if (s + 2 < NS) {
            int nst = sidx + 2; if (nst >= NSTG) nst -= NSTG;
            load_stage(nst, (s + 2) * 64);
            CP_COMMIT();
        }
        const uint32_t sQh = tiles + sidx * ASTAGE_B;
        const uint32_t sQl = sQh + TILE_B;
        const uint32_t sKh = sQh + 2 * TILE_B;
        const uint32_t sKl = sQh + 3 * TILE_B;

        #pragma unroll
        for (int k16 = 0; k16 < 4; k16++) {
            uint32_t ah[4][4], al[4][4], bh[4][2], bl[4][2];
            #pragma unroll
            for (int tm = 0; tm < 4; tm++) {
                uint32_t off = SWZ128((uint32_t)((wm + tm * 16 + rA) * 128 + cA + k16 * 32));
                LDSM_X4(ah[tm], sQh + off);
                LDSM_X4(al[tm], sQl + off);
            }
            #pragma unroll
            for (int p = 0; p < 2; p++) {
                uint32_t off = SWZ128((uint32_t)((wn + p * 16 + rB) * 128 + cB + k16 * 32));
                uint32_t t[4];
                LDSM_X4(t, sKh + off);
                bh[2*p][0] = t[0]; bh[2*p][1] = t[1];
                bh[2*p+1][0] = t[2]; bh[2*p+1][1] = t[3];
                LDSM_X4(t, sKl + off);
                bl[2*p][0] = t[0]; bl[2*p][1] = t[1];
                bl[2*p+1][0] = t[2]; bl[2*p+1][1] = t[3];
            }
            #pragma unroll
            for (int tm = 0; tm < 4; tm++)
                #pragma unroll
                for (int tn = 0; tn < 4; tn++) {
                    mma16816(acc[tm][tn], ah[tm], bh[tn]);
                    mma16816(acc[tm][tn], ah[tm], bl[tn]);
                    mma16816(acc[tm][tn], al[tm], bh[tn]);
                }
        }
        if (++sidx == NSTG) sidx = 0;
        __syncthreads();
    }

    const bool prevok = (wblk > 0);
    const int lr4 = lane >> 2, lc2 = (lane & 3) << 1;
    __half* oh = awh + (size_t)blk * WSZ * 256;
    __half* ol = awl + (size_t)blk * WSZ * 256;
    #pragma unroll
    for (int tm = 0; tm < 4; tm++)
        #pragma unroll
        for (int tn = 0; tn < 4; tn++) {
            #pragma unroll
            for (int half8 = 0; half8 < 2; half8++) {
                int i = wm + tm * 16 + lr4 + half8 * 8;
                int jl = wn + tn * 8 + lc2;
                int j = (jhalf << 7) + jl;
                float r[2];
                #pragma unroll
                for (int u = 0; u < 2; u++) {
                    int jj = j + u;
                    bool keep = (jj >= i) && (jj <= i + WSZ) && (prevok || jj >= WSZ);
                    float sv = acc[tm][tn][half8 * 2 + u];
                    r[u] = (keep && sv > 0.f) ? sv * sv : 0.f;
                }
                write_hl2(oh, ol, (size_t)i * 256 + j, r[0], r[1]);
            }
        }
}

// ---------------- attn_out (HMMA): out = attn @ v2, hi/lo out ----------------
#define VTILE_B  16384
#define OSTAGE_B (2*TILE_B + 2*VTILE_B)
#define AOUT_SMEM (NSTG*OSTAGE_B + 1024)
#define SWZV(off) ((off) ^ ((((off) >> 8) & 7) << 4))

__global__ __launch_bounds__(256, 1) void attn_out_hmma(
    const __half* __restrict__ qkvh, const __half* __restrict__ qkvl,
    const __half* __restrict__ awh, const __half* __restrict__ awl,
    __half* __restrict__ ath, __half* __restrict__ atl)
{
    extern __shared__ char smem[];
    const uint32_t tiles = (smem_u32(smem) + 1023) & ~1023u;
    const int tid = threadIdx.x, wid = tid >> 5, lane = tid & 31;
    const int n0 = blockIdx.x << 7;
    const int blk = blockIdx.y;
    const int b = blk >> 6, wblk = blk & 63;
    const int qbase = b * TT + wblk * WSZ;
    const int krow0 = qbase - WSZ;
    const int bstart = b * TT;
    const int wm = (wid & 1) << 6, wn = (wid >> 1) << 5;

    const __half* Ah = awh + (size_t)blk * WSZ * 256;
    const __half* Al = awl + (size_t)blk * WSZ * 256;

    float acc[4][4][4];
    #pragma unroll
    for (int a = 0; a < 4; a++)
        #pragma unroll
        for (int b2 = 0; b2 < 4; b2++)
            #pragma unroll
            for (int c = 0; c < 4; c++) acc[a][b2][c] = 0.f;

    const int mat = lane >> 3, lr = lane & 7;
    const int rA = ((mat & 1) << 3) + lr, cA = (mat >> 1) << 4;

    auto load_stage = [&](int st, int k0) {
        const uint32_t base = tiles + st * OSTAGE_B;
        #pragma unroll
        for (int i = 0; i < 4; i++) {
            int idx = tid + (i << 8);
            int row = idx >> 3, c = idx & 7;
            size_t off = (size_t)row * 256 + k0 + c * 8;
            uint32_t d = SWZ128(row * 128 + c * 16);
            CPA(base + d, Ah + off);
            CPA(base + TILE_B + d, Al + off);
        }
        #pragma unroll
        for (int i = 0; i < 4; i++) {
            int idx = tid + (i << 8);
            int j = idx >> 4, c = idx & 15;
            int grow = krow0 + k0 + j;
            bool ok = grow >= bstart;
            size_t off = (size_t)grow * TDIM + 2 * DIM + n0 + c * 8;
            uint32_t d = SWZV((uint32_t)(j * 256 + c * 16));
            CPA_Z(base + 2 * TILE_B + d, qkvh + off, ok);
            CPA_Z(base + 2 * TILE_B + VTILE_B + d, qkvl + off, ok);
        }
    };

    const int NS = 4;
    load_stage(0, 0);
    CP_COMMIT();
    load_stage(1, 64);
    CP_COMMIT();

    int sidx = 0;
    for (int s = 0; s < NS; s++) {
        CP_WAIT(1);
        __syncthreads();
        if (s + 2 < NS) {
            int nst = sidx + 2; if (nst >= NSTG) nst -= NSTG;
            load_stage(nst, (s + 2) * 64);
            CP_COMMIT();
        }
        const uint32_t sAh = tiles + sidx * OSTAGE_B;
        const uint32_t sAl = sAh + TILE_B;
        const uint32_t sVh = sAh + 2 * TILE_B;
        const uint32_t sVl = sVh + VTILE_B;

        #pragma unroll
        for (int k16 = 0; k16 < 4; k16++) {
            uint32_t ah[4][4], al[4][4], bh[4][2], bl[4][2];
            #pragma unroll
            for (int tm = 0; tm < 4; tm++) {
                uint32_t off = SWZ128((uint32_t)((wm + tm * 16 + rA) * 128 + cA + k16 * 32));
                LDSM_X4(ah[tm], sAh + off);
                LDSM_X4(al[tm], sAl + off);
            }
            #pragma unroll
            for (int p = 0; p < 2; p++) {
                int nn = wn + p * 16;
                uint32_t off = SWZV((uint32_t)((k16 * 16 + (lane & 15)) * 256 + (nn + ((lane >> 4) << 3)) * 2));
                uint32_t t[4];
                LDSM_X4_T(t, sVh + off);
                bh[2*p][0] = t[0]; bh[2*p][1] = t[1];
                bh[2*p+1][0] = t[2]; bh[2*p+1][1] = t[3];
                LDSM_X4_T(t, sVl + off);
                bl[2*p][0] = t[0]; bl[2*p][1] = t[1];
                bl[2*p+1][0] = t[2]; bl[2*p+1][1] = t[3];
            }
            #pragma unroll
            for (int tm = 0; tm < 4; tm++)
                #pragma unroll
                for (int tn = 0; tn < 4; tn++) {
                    mma16816(acc[tm][tn], ah[tm], bh[tn]);
                    mma16816(acc[tm][tn], ah[tm], bl[tn]);
                    mma16816(acc[tm][tn], al[tm], bh[tn]);
                }
        }
        if (++sidx == NSTG) sidx = 0;
        __syncthreads();
    }

    const int lr4 = lane >> 2, lc2 = (lane & 3) << 1;
    #pragma unroll
    for (int tm = 0; tm < 4; tm++)
        #pragma unroll
        for (int tn = 0; tn < 4; tn++) {
            int gr = qbase + wm + tm * 16 + lr4;
            int gc = n0 + wn + tn * 8 + lc2;
            write_hl2(ath, atl, (size_t)gr * DIM + gc, acc[tm][tn][0], acc[tm][tn][1]);
            write_hl2(ath, atl, (size_t)(gr + 8) * DIM + gc, acc[tm][tn][2], acc[tm][tn][3]);
        }
}

// ---------------------------------------------------------------------------
extern "C" void kernel_launch(void* const* d_in, const int* in_sizes, int n_in,
                              void* d_out, int out_size)
{
    (void)in_sizes; (void)n_in; (void)out_size;
    const float* x      = (const float*)d_in[0];
    const float* w_attn = (const float*)d_in[1];
    const float* w_o    = (const float*)d_in[2];
    float* out = (float*)d_out;

    __half *xh, *xl, *wah, *woh, *qkvh, *qkvl, *awh, *awl, *ath, *atl;
    cudaGetSymbolAddress((void**)&xh,   g_xh);   cudaGetSymbolAddress((void**)&xl,   g_xl);
    cudaGetSymbolAddress((void**)&wah,  g_wah);  cudaGetSymbolAddress((void**)&woh,  g_woh);
    cudaGetSymbolAddress((void**)&qkvh, g_qkvh); cudaGetSymbolAddress((void**)&qkvl, g_qkvl);
    cudaGetSymbolAddress((void**)&awh,  g_awh);  cudaGetSymbolAddress((void**)&awl,  g_awl);
    cudaGetSymbolAddress((void**)&ath,  g_ath);  cudaGetSymbolAddress((void**)&atl,  g_atl);

    cudaFuncSetAttribute(gemm_hmma<0>, cudaFuncAttributeMaxDynamicSharedMemorySize, GEMM_SMEM);
    cudaFuncSetAttribute(gemm_hmma<1>, cudaFuncAttributeMaxDynamicSharedMemorySize, GEMM_SMEM);
    cudaFuncSetAttribute(attn_sim_hmma, cudaFuncAttributeMaxDynamicSharedMemorySize, ASIM_SMEM);
    cudaFuncSetAttribute(attn_out_hmma, cudaFuncAttributeMaxDynamicSharedMemorySize, AOUT_SMEM);

    // 0) fp16 splits
    {
        int n4 = MROWS * DIM / 4;
        split_hl_kernel<<<(n4 + 255) / 256, 256>>>(x, xh, xl, n4);
        n4 = TDIM * DIM / 4;
        split_h_kernel<<<(n4 + 255) / 256, 256>>>(w_attn, wah, n4);
        n4 = DIM * DIM / 4;
        split_h_kernel<<<(n4 + 255) / 256, 256>>>(w_o, woh, n4);
    }

    // 1) qkv = x @ w_attn^T -> hi/lo fp16  (q cols scaled by 1/W)
    gemm_hmma<1><<<dim3(TDIM / 128, MROWS / 128), 256, GEMM_SMEM>>>(
        xh, xl, wah, nullptr, qkvh, qkvl, MROWS, TDIM, DIM, DIM, 1.0f / (float)WSZ);

    // 2) attention weights (HMMA) -> hi/lo fp16
    attn_sim_hmma<<<dim3(2, NBLK), 256, ASIM_SMEM>>>(qkvh, qkvl, awh, awl);

    // 3) attn @ v (HMMA) -> hi/lo fp16
    attn_out_hmma<<<dim3(DIM / 128, NBLK), 256, AOUT_SMEM>>>(
        qkvh, qkvl, awh, awl, ath, atl);

    // 4) out = att @ w_o^T -> fp32
    gemm_hmma<0><<<dim3(DIM / 128, MROWS / 128), 256, GEMM_SMEM>>>(
        ath, atl, woh, out, nullptr, nullptr, MROWS, DIM, DIM, 0, 1.0f);
}